// round 3
// baseline (speedup 1.0000x reference)
#include <cuda_runtime.h>
#include <cstdint>

// Problem constants (fixed-shape problem)
#define NN     100000      // nodes
#define FF     256         // input dim
#define HC     128         // H*C = 2*64
#define EBASE  1600000     // edges before self loops
#define ETOT   1700000     // edges + N self loops

// ---------------------------------------------------------------------------
// Scratch (no cudaMalloc allowed -> __device__ globals)
// ---------------------------------------------------------------------------
__device__ float d_xl[(size_t)NN * HC];     // 51.2 MB  projected source feats
__device__ float d_xr[(size_t)NN * HC];     // 51.2 MB  projected target feats
__device__ float d_p[(size_t)ETOT * 2];     // 13.6 MB  logits -> unnormalized probs
__device__ float d_m[(size_t)NN * 2];       // per-(dst,head) running max
__device__ float d_den[(size_t)NN * 2];     // per-(dst,head) softmax denom

// ---------------------------------------------------------------------------
// Init: out = bias (broadcast), m = -inf, denom = 0
// ---------------------------------------------------------------------------
__global__ void init_kernel(const float* __restrict__ bias, float* __restrict__ out) {
    int i = blockIdx.x * 256 + threadIdx.x;
    if (i < NN * HC) out[i] = bias[i & (HC - 1)];
    if (i < NN * 2) {
        d_m[i]   = __int_as_float(0xff800000);  // -inf
        d_den[i] = 0.0f;
    }
}

// ---------------------------------------------------------------------------
// Projection GEMM: xl = x @ Wl^T + bl ; xr = x @ Wr^T + br
// blockIdx.x selects Wl (0) or Wr (1); each block does a 128x128 output tile
// (128 rows of nodes x the full 128 output channels). 8x8 microtile/thread.
// ---------------------------------------------------------------------------
__global__ void __launch_bounds__(256) proj_kernel(
    const float* __restrict__ x,
    const float* __restrict__ Wl, const float* __restrict__ bl,
    const float* __restrict__ Wr, const float* __restrict__ br)
{
    __shared__ float As[16][132];   // k-major, padded
    __shared__ float Bs[16][132];

    const int nblk = blockIdx.x;                // 0 -> xl, 1 -> xr
    const int row0 = blockIdx.y * 128;
    const float* __restrict__ W  = nblk ? Wr : Wl;
    const float* __restrict__ bv = nblk ? br : bl;
    float* __restrict__ out = nblk ? d_xr : d_xl;

    const int tid = threadIdx.x;
    const int tx = tid & 15;        // output-col group
    const int ty = tid >> 4;        // output-row group

    float acc[8][8];
#pragma unroll
    for (int i = 0; i < 8; i++)
#pragma unroll
        for (int j = 0; j < 8; j++) acc[i][j] = 0.0f;

    for (int k0 = 0; k0 < FF; k0 += 16) {
#pragma unroll
        for (int t = 0; t < 2; t++) {
            int idx = tid + t * 256;        // 0..511
            int r   = idx >> 2;             // 0..127
            int c4  = idx & 3;              // which float4 of the 16-k chunk
            // x tile (rows of nodes)
            float4 xv = make_float4(0.f, 0.f, 0.f, 0.f);
            int grow = row0 + r;
            if (grow < NN)
                xv = *(const float4*)(x + (size_t)grow * FF + k0 + c4 * 4);
            As[c4 * 4 + 0][r] = xv.x;
            As[c4 * 4 + 1][r] = xv.y;
            As[c4 * 4 + 2][r] = xv.z;
            As[c4 * 4 + 3][r] = xv.w;
            // W tile (rows of W = output channels, full 128 covered)
            float4 wv = *(const float4*)(W + (size_t)r * FF + k0 + c4 * 4);
            Bs[c4 * 4 + 0][r] = wv.x;
            Bs[c4 * 4 + 1][r] = wv.y;
            Bs[c4 * 4 + 2][r] = wv.z;
            Bs[c4 * 4 + 3][r] = wv.w;
        }
        __syncthreads();

#pragma unroll
        for (int kk = 0; kk < 16; kk++) {
            float a[8], b[8];
            *(float4*)(a)     = *(const float4*)&As[kk][ty * 8];
            *(float4*)(a + 4) = *(const float4*)&As[kk][ty * 8 + 4];
            *(float4*)(b)     = *(const float4*)&Bs[kk][tx * 8];
            *(float4*)(b + 4) = *(const float4*)&Bs[kk][tx * 8 + 4];
#pragma unroll
            for (int i = 0; i < 8; i++)
#pragma unroll
                for (int j = 0; j < 8; j++)
                    acc[i][j] = fmaf(a[i], b[j], acc[i][j]);
        }
        __syncthreads();
    }

    // epilogue: add linear bias, store float4s
    float bb[8];
#pragma unroll
    for (int j = 0; j < 8; j++) bb[j] = bv[tx * 8 + j];

#pragma unroll
    for (int i = 0; i < 8; i++) {
        int grow = row0 + ty * 8 + i;
        if (grow >= NN) continue;
        float* op = out + (size_t)grow * HC + tx * 8;
        float4 v0, v1;
        v0.x = acc[i][0] + bb[0]; v0.y = acc[i][1] + bb[1];
        v0.z = acc[i][2] + bb[2]; v0.w = acc[i][3] + bb[3];
        v1.x = acc[i][4] + bb[4]; v1.y = acc[i][5] + bb[5];
        v1.z = acc[i][6] + bb[6]; v1.w = acc[i][7] + bb[7];
        *(float4*)(op)     = v0;
        *(float4*)(op + 4) = v1;
    }
}

// ---------------------------------------------------------------------------
// Float atomic max via monotonic int/uint trick (init must be -inf)
// ---------------------------------------------------------------------------
__device__ __forceinline__ void atomicMaxF(float* addr, float v) {
    if (v >= 0.0f)
        atomicMax((int*)addr, __float_as_int(v));
    else
        atomicMin((unsigned int*)addr, __float_as_uint(v));
}

// ---------------------------------------------------------------------------
// Pass B: per-edge logits + segment max.
// One warp per edge. Lane l reads float4 at channel 4l; lanes 0-15 = head0,
// lanes 16-31 = head1. Width-16 shuffle reduction per head.
// ---------------------------------------------------------------------------
__global__ void __launch_bounds__(256) edge_logits_kernel(
    const int* __restrict__ ei, const float* __restrict__ att)
{
    int e = blockIdx.x * 8 + (threadIdx.x >> 5);
    if (e >= ETOT) return;
    int lane = threadIdx.x & 31;

    int src, dst;
    if (e < EBASE) { src = __ldg(ei + e); dst = __ldg(ei + EBASE + e); }
    else           { src = e - EBASE;     dst = src; }

    float4 a = *(const float4*)(d_xl + (size_t)src * HC + lane * 4);
    float4 b = *(const float4*)(d_xr + (size_t)dst * HC + lane * 4);
    float4 w = *(const float4*)(att + lane * 4);

    float e0 = a.x + b.x, e1 = a.y + b.y, e2 = a.z + b.z, e3 = a.w + b.w;
    e0 = e0 > 0.f ? e0 : 0.2f * e0;
    e1 = e1 > 0.f ? e1 : 0.2f * e1;
    e2 = e2 > 0.f ? e2 : 0.2f * e2;
    e3 = e3 > 0.f ? e3 : 0.2f * e3;
    float s = w.x * e0 + w.y * e1 + w.z * e2 + w.w * e3;

    // reduce within each 16-lane half (one per head)
    s += __shfl_down_sync(0xffffffffu, s, 8, 16);
    s += __shfl_down_sync(0xffffffffu, s, 4, 16);
    s += __shfl_down_sync(0xffffffffu, s, 2, 16);
    s += __shfl_down_sync(0xffffffffu, s, 1, 16);

    if (lane == 0) {
        d_p[(size_t)e * 2 + 0] = s;
        atomicMaxF(&d_m[(size_t)dst * 2 + 0], s);
    } else if (lane == 16) {
        d_p[(size_t)e * 2 + 1] = s;
        atomicMaxF(&d_m[(size_t)dst * 2 + 1], s);
    }
}

// ---------------------------------------------------------------------------
// Pass C: p = exp(logit - m[dst]); denom += p. Thread per edge.
// ---------------------------------------------------------------------------
__global__ void __launch_bounds__(256) edge_exp_kernel(const int* __restrict__ ei)
{
    int e = blockIdx.x * 256 + threadIdx.x;
    if (e >= ETOT) return;
    int dst = (e < EBASE) ? __ldg(ei + EBASE + e) : (e - EBASE);

    float2 lg = *(const float2*)(d_p + (size_t)e * 2);
    float m0 = d_m[(size_t)dst * 2 + 0];
    float m1 = d_m[(size_t)dst * 2 + 1];
    float p0 = __expf(lg.x - m0);
    float p1 = __expf(lg.y - m1);
    *(float2*)(d_p + (size_t)e * 2) = make_float2(p0, p1);
    atomicAdd(&d_den[(size_t)dst * 2 + 0], p0);
    atomicAdd(&d_den[(size_t)dst * 2 + 1], p1);
}

// ---------------------------------------------------------------------------
// Pass D: out[dst] += alpha * xl[src]. Warp per edge, vector red.global.add.
// ---------------------------------------------------------------------------
__global__ void __launch_bounds__(256) edge_aggregate_kernel(
    const int* __restrict__ ei, float* __restrict__ out)
{
    int e = blockIdx.x * 8 + (threadIdx.x >> 5);
    if (e >= ETOT) return;
    int lane = threadIdx.x & 31;

    int src, dst;
    if (e < EBASE) { src = __ldg(ei + e); dst = __ldg(ei + EBASE + e); }
    else           { src = e - EBASE;     dst = src; }

    int h = lane >> 4;   // head for this lane's channels
    float alpha = d_p[(size_t)e * 2 + h] / d_den[(size_t)dst * 2 + h];

    float4 v = *(const float4*)(d_xl + (size_t)src * HC + lane * 4);
    float vx = v.x * alpha, vy = v.y * alpha, vz = v.z * alpha, vw = v.w * alpha;
    float* o = out + (size_t)dst * HC + lane * 4;
    asm volatile("red.global.add.v4.f32 [%0], {%1, %2, %3, %4};"
                 :: "l"(o), "f"(vx), "f"(vy), "f"(vz), "f"(vw)
                 : "memory");
}

// ---------------------------------------------------------------------------
// Launch
// ---------------------------------------------------------------------------
extern "C" void kernel_launch(void* const* d_in, const int* in_sizes, int n_in,
                              void* d_out, int out_size)
{
    const float* x    = (const float*)d_in[0];
    const float* Wl   = (const float*)d_in[1];
    const float* bl   = (const float*)d_in[2];
    const float* Wr   = (const float*)d_in[3];
    const float* br   = (const float*)d_in[4];
    const float* att  = (const float*)d_in[5];
    const float* bias = (const float*)d_in[6];
    const int*   ei   = (const int*)d_in[7];
    float* out = (float*)d_out;

    // 1) init out=bias, m=-inf, denom=0
    init_kernel<<<(NN * HC + 255) / 256, 256>>>(bias, out);

    // 2) projections xl, xr
    dim3 pg(2, (NN + 127) / 128);
    proj_kernel<<<pg, 256>>>(x, Wl, bl, Wr, br);

    // 3) per-edge logits + segment max
    edge_logits_kernel<<<(ETOT + 7) / 8, 256>>>(ei, att);

    // 4) exp + segment sum
    edge_exp_kernel<<<(ETOT + 255) / 256, 256>>>(ei);

    // 5) weighted scatter-add aggregation
    edge_aggregate_kernel<<<(ETOT + 7) / 8, 256>>>(ei, out);
}

// round 4
// speedup vs baseline: 1.2042x; 1.2042x over previous
#include <cuda_runtime.h>
#include <cstdint>

// Problem constants (fixed-shape problem)
#define NN     100000      // nodes
#define FF     256         // input dim
#define HC     128         // H*C = 2*64
#define EBASE  1600000     // edges before self loops
#define ETOT   1700000     // edges + N self loops

// ---------------------------------------------------------------------------
// Scratch (no cudaMalloc allowed -> __device__ globals)
// ---------------------------------------------------------------------------
__device__ float d_xl[(size_t)NN * HC];     // 51.2 MB  projected source feats
__device__ float d_xr[(size_t)NN * HC];     // 51.2 MB  projected target feats
__device__ float d_p[(size_t)ETOT * 2];     // 13.6 MB  logits -> unnormalized probs
__device__ float d_m[(size_t)NN * 2];       // per-(dst,head) running max
__device__ float d_den[(size_t)NN * 2];     // per-(dst,head) softmax denom

// ---------------------------------------------------------------------------
// Init: out = bias (broadcast), m = -inf, denom = 0
// ---------------------------------------------------------------------------
__global__ void init_kernel(const float* __restrict__ bias, float* __restrict__ out) {
    int i = blockIdx.x * 256 + threadIdx.x;
    if (i < NN * HC) out[i] = bias[i & (HC - 1)];
    if (i < NN * 2) {
        d_m[i]   = __int_as_float(0xff800000);  // -inf
        d_den[i] = 0.0f;
    }
}

// ---------------------------------------------------------------------------
// TF32 helpers
// ---------------------------------------------------------------------------
__device__ __forceinline__ uint32_t f2tf32(float f) {
    uint32_t u;
    asm("cvt.rna.tf32.f32 %0, %1;" : "=r"(u) : "f"(f));
    return u;
}

__device__ __forceinline__ void mma_tf32(float* d, const uint32_t* a,
                                         uint32_t b0, uint32_t b1) {
    asm volatile(
        "mma.sync.aligned.m16n8k8.row.col.f32.tf32.tf32.f32 "
        "{%0,%1,%2,%3}, {%4,%5,%6,%7}, {%8,%9}, {%0,%1,%2,%3};\n"
        : "+f"(d[0]), "+f"(d[1]), "+f"(d[2]), "+f"(d[3])
        : "r"(a[0]), "r"(a[1]), "r"(a[2]), "r"(a[3]), "r"(b0), "r"(b1));
}

// ---------------------------------------------------------------------------
// Projection GEMM (TF32 tensor cores):
//   xl = x @ Wl^T + bl ; xr = x @ Wr^T + br
// blockIdx.x selects Wl (0) / Wr (1). Block tile: 128 nodes x 128 channels.
// 8 warps laid out 4(M) x 2(N); warp tile 32x64 via m16n8k8 fragments.
// Smem rows padded to stride 20 words -> conflict-free fragment LDS.
// ---------------------------------------------------------------------------
#define KT 16      // K-tile
#define AST 20     // padded smem row stride (words)

__global__ void __launch_bounds__(256) proj_tf32_kernel(
    const float* __restrict__ x,
    const float* __restrict__ Wl, const float* __restrict__ bl,
    const float* __restrict__ Wr, const float* __restrict__ br)
{
    __shared__ uint32_t Ax[128 * AST];
    __shared__ uint32_t Bw[128 * AST];

    const int nblk = blockIdx.x;                 // 0 -> xl, 1 -> xr
    const int row0 = blockIdx.y * 128;
    const float* __restrict__ W  = nblk ? Wr : Wl;
    const float* __restrict__ bv = nblk ? br : bl;
    float* __restrict__ out = nblk ? d_xr : d_xl;

    const int tid    = threadIdx.x;
    const int warp   = tid >> 5;
    const int lane   = tid & 31;
    const int warp_m = warp & 3;                 // 0..3 -> m32 tile
    const int warp_n = warp >> 2;                // 0..1 -> n64 tile
    const int qr     = lane >> 2;                // fragment row group 0..7
    const int qc     = lane & 3;                 // fragment col group 0..3

    float acc[2][8][4];
#pragma unroll
    for (int mf = 0; mf < 2; mf++)
#pragma unroll
        for (int nf = 0; nf < 8; nf++)
#pragma unroll
            for (int i = 0; i < 4; i++) acc[mf][nf][i] = 0.0f;

    for (int k0 = 0; k0 < FF; k0 += KT) {
        // Load 128x16 tiles of x and W, converting to tf32 on the way in.
#pragma unroll
        for (int t = 0; t < 2; t++) {
            int idx = tid + t * 256;             // 0..511
            int r   = idx >> 2;                  // 0..127
            int c4  = (idx & 3) * 4;             // 0,4,8,12
            float4 xv = make_float4(0.f, 0.f, 0.f, 0.f);
            if (row0 + r < NN)
                xv = *(const float4*)(x + (size_t)(row0 + r) * FF + k0 + c4);
            Ax[r * AST + c4 + 0] = f2tf32(xv.x);
            Ax[r * AST + c4 + 1] = f2tf32(xv.y);
            Ax[r * AST + c4 + 2] = f2tf32(xv.z);
            Ax[r * AST + c4 + 3] = f2tf32(xv.w);
            float4 wv = *(const float4*)(W + (size_t)r * FF + k0 + c4);
            Bw[r * AST + c4 + 0] = f2tf32(wv.x);
            Bw[r * AST + c4 + 1] = f2tf32(wv.y);
            Bw[r * AST + c4 + 2] = f2tf32(wv.z);
            Bw[r * AST + c4 + 3] = f2tf32(wv.w);
        }
        __syncthreads();

#pragma unroll
        for (int ks = 0; ks < KT; ks += 8) {
            uint32_t a[2][4];
#pragma unroll
            for (int mf = 0; mf < 2; mf++) {
                int mr = warp_m * 32 + mf * 16 + qr;
                a[mf][0] = Ax[mr * AST + ks + qc];
                a[mf][1] = Ax[(mr + 8) * AST + ks + qc];
                a[mf][2] = Ax[mr * AST + ks + qc + 4];
                a[mf][3] = Ax[(mr + 8) * AST + ks + qc + 4];
            }
#pragma unroll
            for (int nf = 0; nf < 8; nf++) {
                int nc = warp_n * 64 + nf * 8 + qr;
                uint32_t b0 = Bw[nc * AST + ks + qc];
                uint32_t b1 = Bw[nc * AST + ks + qc + 4];
                mma_tf32(acc[0][nf], a[0], b0, b1);
                mma_tf32(acc[1][nf], a[1], b0, b1);
            }
        }
        __syncthreads();
    }

    // Epilogue: add bias, float2 stores (C frag: rows qr/qr+8, cols 2*qc,2*qc+1)
#pragma unroll
    for (int mf = 0; mf < 2; mf++) {
#pragma unroll
        for (int nf = 0; nf < 8; nf++) {
            int col = warp_n * 64 + nf * 8 + qc * 2;
            float b0 = bv[col], b1 = bv[col + 1];
            int row = row0 + warp_m * 32 + mf * 16 + qr;
            if (row < NN) {
                float2 v = make_float2(acc[mf][nf][0] + b0, acc[mf][nf][1] + b1);
                *(float2*)(out + (size_t)row * HC + col) = v;
            }
            if (row + 8 < NN) {
                float2 v = make_float2(acc[mf][nf][2] + b0, acc[mf][nf][3] + b1);
                *(float2*)(out + (size_t)(row + 8) * HC + col) = v;
            }
        }
    }
}

// ---------------------------------------------------------------------------
// Float atomic max via monotonic int/uint trick (init must be -inf)
// ---------------------------------------------------------------------------
__device__ __forceinline__ void atomicMaxF(float* addr, float v) {
    if (v >= 0.0f)
        atomicMax((int*)addr, __float_as_int(v));
    else
        atomicMin((unsigned int*)addr, __float_as_uint(v));
}

// ---------------------------------------------------------------------------
// Pass B: per-edge logits + segment max.
// One warp per edge. Lane l reads float4 at channel 4l; lanes 0-15 = head0,
// lanes 16-31 = head1. Width-16 shuffle reduction per head.
// ---------------------------------------------------------------------------
__global__ void __launch_bounds__(256) edge_logits_kernel(
    const int* __restrict__ ei, const float* __restrict__ att)
{
    int e = blockIdx.x * 8 + (threadIdx.x >> 5);
    if (e >= ETOT) return;
    int lane = threadIdx.x & 31;

    int src, dst;
    if (e < EBASE) { src = __ldg(ei + e); dst = __ldg(ei + EBASE + e); }
    else           { src = e - EBASE;     dst = src; }

    float4 a = *(const float4*)(d_xl + (size_t)src * HC + lane * 4);
    float4 b = *(const float4*)(d_xr + (size_t)dst * HC + lane * 4);
    float4 w = *(const float4*)(att + lane * 4);

    float e0 = a.x + b.x, e1 = a.y + b.y, e2 = a.z + b.z, e3 = a.w + b.w;
    e0 = e0 > 0.f ? e0 : 0.2f * e0;
    e1 = e1 > 0.f ? e1 : 0.2f * e1;
    e2 = e2 > 0.f ? e2 : 0.2f * e2;
    e3 = e3 > 0.f ? e3 : 0.2f * e3;
    float s = w.x * e0 + w.y * e1 + w.z * e2 + w.w * e3;

    // reduce within each 16-lane half (one per head)
    s += __shfl_down_sync(0xffffffffu, s, 8, 16);
    s += __shfl_down_sync(0xffffffffu, s, 4, 16);
    s += __shfl_down_sync(0xffffffffu, s, 2, 16);
    s += __shfl_down_sync(0xffffffffu, s, 1, 16);

    if (lane == 0) {
        d_p[(size_t)e * 2 + 0] = s;
        atomicMaxF(&d_m[(size_t)dst * 2 + 0], s);
    } else if (lane == 16) {
        d_p[(size_t)e * 2 + 1] = s;
        atomicMaxF(&d_m[(size_t)dst * 2 + 1], s);
    }
}

// ---------------------------------------------------------------------------
// Pass C: p = exp(logit - m[dst]); denom += p. Thread per edge.
// ---------------------------------------------------------------------------
__global__ void __launch_bounds__(256) edge_exp_kernel(const int* __restrict__ ei)
{
    int e = blockIdx.x * 256 + threadIdx.x;
    if (e >= ETOT) return;
    int dst = (e < EBASE) ? __ldg(ei + EBASE + e) : (e - EBASE);

    float2 lg = *(const float2*)(d_p + (size_t)e * 2);
    float m0 = d_m[(size_t)dst * 2 + 0];
    float m1 = d_m[(size_t)dst * 2 + 1];
    float p0 = __expf(lg.x - m0);
    float p1 = __expf(lg.y - m1);
    *(float2*)(d_p + (size_t)e * 2) = make_float2(p0, p1);
    atomicAdd(&d_den[(size_t)dst * 2 + 0], p0);
    atomicAdd(&d_den[(size_t)dst * 2 + 1], p1);
}

// ---------------------------------------------------------------------------
// Pass D: out[dst] += alpha * xl[src]. Warp per edge, vector red.global.add.
// ---------------------------------------------------------------------------
__global__ void __launch_bounds__(256) edge_aggregate_kernel(
    const int* __restrict__ ei, float* __restrict__ out)
{
    int e = blockIdx.x * 8 + (threadIdx.x >> 5);
    if (e >= ETOT) return;
    int lane = threadIdx.x & 31;

    int src, dst;
    if (e < EBASE) { src = __ldg(ei + e); dst = __ldg(ei + EBASE + e); }
    else           { src = e - EBASE;     dst = src; }

    int h = lane >> 4;   // head for this lane's channels
    float alpha = d_p[(size_t)e * 2 + h] / d_den[(size_t)dst * 2 + h];

    float4 v = *(const float4*)(d_xl + (size_t)src * HC + lane * 4);
    float vx = v.x * alpha, vy = v.y * alpha, vz = v.z * alpha, vw = v.w * alpha;
    float* o = out + (size_t)dst * HC + lane * 4;
    asm volatile("red.global.add.v4.f32 [%0], {%1, %2, %3, %4};"
                 :: "l"(o), "f"(vx), "f"(vy), "f"(vz), "f"(vw)
                 : "memory");
}

// ---------------------------------------------------------------------------
// Launch
// ---------------------------------------------------------------------------
extern "C" void kernel_launch(void* const* d_in, const int* in_sizes, int n_in,
                              void* d_out, int out_size)
{
    const float* x    = (const float*)d_in[0];
    const float* Wl   = (const float*)d_in[1];
    const float* bl   = (const float*)d_in[2];
    const float* Wr   = (const float*)d_in[3];
    const float* br   = (const float*)d_in[4];
    const float* att  = (const float*)d_in[5];
    const float* bias = (const float*)d_in[6];
    const int*   ei   = (const int*)d_in[7];
    float* out = (float*)d_out;

    // 1) init out=bias, m=-inf, denom=0
    init_kernel<<<(NN * HC + 255) / 256, 256>>>(bias, out);

    // 2) projections xl, xr (TF32 tensor cores)
    dim3 pg(2, (NN + 127) / 128);
    proj_tf32_kernel<<<pg, 256>>>(x, Wl, bl, Wr, br);

    // 3) per-edge logits + segment max
    edge_logits_kernel<<<(ETOT + 7) / 8, 256>>>(ei, att);

    // 4) exp + segment sum
    edge_exp_kernel<<<(ETOT + 255) / 256, 256>>>(ei);

    // 5) weighted scatter-add aggregation
    edge_aggregate_kernel<<<(ETOT + 7) / 8, 256>>>(ei, out);
}

// round 5
// speedup vs baseline: 1.2118x; 1.0064x over previous
#include <cuda_runtime.h>
#include <cstdint>

// Problem constants (fixed-shape problem)
#define NN     100000      // nodes
#define FF     256         // input dim
#define HC     128         // H*C = 2*64
#define EBASE  1600000     // edges before self loops
#define ETOT   1700000     // edges + N self loops

// ---------------------------------------------------------------------------
// Scratch (no cudaMalloc allowed -> __device__ globals)
// ---------------------------------------------------------------------------
__device__ float d_xl[(size_t)NN * HC];     // 51.2 MB  projected source feats
__device__ float d_xr[(size_t)NN * HC];     // 51.2 MB  projected target feats
__device__ float d_p[(size_t)ETOT * 2];     // 13.6 MB  logits per edge/head
__device__ float d_m[(size_t)NN * 2];       // per-(dst,head) running max
__device__ float d_den[(size_t)NN * 2];     // per-(dst,head) softmax denom

// ---------------------------------------------------------------------------
// Init: out = 0 (accumulator), m = -inf, denom = 0
// ---------------------------------------------------------------------------
__global__ void init_kernel(float* __restrict__ out) {
    int i = blockIdx.x * 256 + threadIdx.x;
    if (i < NN * (HC / 4)) ((float4*)out)[i] = make_float4(0.f, 0.f, 0.f, 0.f);
    if (i < NN * 2) {
        d_m[i]   = __int_as_float(0xff800000);  // -inf
        d_den[i] = 0.0f;
    }
}

// ---------------------------------------------------------------------------
// TF32 helpers
// ---------------------------------------------------------------------------
__device__ __forceinline__ uint32_t f2tf32(float f) {
    uint32_t u;
    asm("cvt.rna.tf32.f32 %0, %1;" : "=r"(u) : "f"(f));
    return u;
}

__device__ __forceinline__ void mma_tf32(float* d, const uint32_t* a,
                                         uint32_t b0, uint32_t b1) {
    asm volatile(
        "mma.sync.aligned.m16n8k8.row.col.f32.tf32.tf32.f32 "
        "{%0,%1,%2,%3}, {%4,%5,%6,%7}, {%8,%9}, {%0,%1,%2,%3};\n"
        : "+f"(d[0]), "+f"(d[1]), "+f"(d[2]), "+f"(d[3])
        : "r"(a[0]), "r"(a[1]), "r"(a[2]), "r"(a[3]), "r"(b0), "r"(b1));
}

// ---------------------------------------------------------------------------
// Fused projection GEMM (TF32): one pass over x computes BOTH
//   xl = x @ Wl^T + bl   and   xr = x @ Wr^T + br.
// Block tile: 128 nodes x 256 output cols (cols 0-127 -> xl, 128-255 -> xr).
// 512 threads = 16 warps as 4(M) x 4(N); warp tile 32x64 via m16n8k8.
// Smem rows padded to stride 20 words -> conflict-free fragment LDS.
// ---------------------------------------------------------------------------
#define KT 16      // K-tile
#define AST 20     // padded smem row stride (words)

__global__ void __launch_bounds__(512) proj_fused_kernel(
    const float* __restrict__ x,
    const float* __restrict__ Wl, const float* __restrict__ bl,
    const float* __restrict__ Wr, const float* __restrict__ br)
{
    __shared__ uint32_t Ax[128 * AST];   // 10.24 KB
    __shared__ uint32_t Bw[256 * AST];   // 20.48 KB

    const int row0 = blockIdx.x * 128;

    const int tid    = threadIdx.x;
    const int warp   = tid >> 5;
    const int lane   = tid & 31;
    const int warp_m = warp & 3;                 // 0..3 -> m32 tile
    const int warp_n = warp >> 2;                // 0..3 -> n64 tile
    const int qr     = lane >> 2;                // fragment row group 0..7
    const int qc     = lane & 3;                 // fragment col group 0..3

    float acc[2][8][4];
#pragma unroll
    for (int mf = 0; mf < 2; mf++)
#pragma unroll
        for (int nf = 0; nf < 8; nf++)
#pragma unroll
            for (int i = 0; i < 4; i++) acc[mf][nf][i] = 0.0f;

    for (int k0 = 0; k0 < FF; k0 += KT) {
        // Load 128x16 x-tile + 256x16 W-tile (Wl rows 0-127, Wr rows 128-255),
        // converting to tf32 on the way into smem. 1536 float4 loads / 512 thr.
#pragma unroll
        for (int t = 0; t < 3; t++) {
            int idx = tid + t * 512;             // 0..1535
            if (idx < 512) {                     // A: x rows
                int r  = idx >> 2;
                int c4 = (idx & 3) * 4;
                float4 xv = make_float4(0.f, 0.f, 0.f, 0.f);
                if (row0 + r < NN)
                    xv = *(const float4*)(x + (size_t)(row0 + r) * FF + k0 + c4);
                Ax[r * AST + c4 + 0] = f2tf32(xv.x);
                Ax[r * AST + c4 + 1] = f2tf32(xv.y);
                Ax[r * AST + c4 + 2] = f2tf32(xv.z);
                Ax[r * AST + c4 + 3] = f2tf32(xv.w);
            } else {                             // B: Wl then Wr
                int i2 = idx - 512;              // 0..1023
                int r  = i2 >> 2;                // 0..255
                int c4 = (i2 & 3) * 4;
                const float* Wp = (r < 128) ? (Wl + (size_t)r * FF)
                                            : (Wr + (size_t)(r - 128) * FF);
                float4 wv = *(const float4*)(Wp + k0 + c4);
                Bw[r * AST + c4 + 0] = f2tf32(wv.x);
                Bw[r * AST + c4 + 1] = f2tf32(wv.y);
                Bw[r * AST + c4 + 2] = f2tf32(wv.z);
                Bw[r * AST + c4 + 3] = f2tf32(wv.w);
            }
        }
        __syncthreads();

#pragma unroll
        for (int ks = 0; ks < KT; ks += 8) {
            uint32_t a[2][4];
#pragma unroll
            for (int mf = 0; mf < 2; mf++) {
                int mr = warp_m * 32 + mf * 16 + qr;
                a[mf][0] = Ax[mr * AST + ks + qc];
                a[mf][1] = Ax[(mr + 8) * AST + ks + qc];
                a[mf][2] = Ax[mr * AST + ks + qc + 4];
                a[mf][3] = Ax[(mr + 8) * AST + ks + qc + 4];
            }
#pragma unroll
            for (int nf = 0; nf < 8; nf++) {
                int nc = warp_n * 64 + nf * 8 + qr;
                uint32_t b0 = Bw[nc * AST + ks + qc];
                uint32_t b1 = Bw[nc * AST + ks + qc + 4];
                mma_tf32(acc[0][nf], a[0], b0, b1);
                mma_tf32(acc[1][nf], a[1], b0, b1);
            }
        }
        __syncthreads();
    }

    // Epilogue. warp_n 0,1 -> xl half; warp_n 2,3 -> xr half (uniform per warp).
    float* __restrict__ out = (warp_n < 2) ? d_xl : d_xr;
    const float* __restrict__ bv = (warp_n < 2) ? bl : br;
    const int colbase = (warp_n & 1) * 64;

#pragma unroll
    for (int mf = 0; mf < 2; mf++) {
#pragma unroll
        for (int nf = 0; nf < 8; nf++) {
            int col = colbase + nf * 8 + qc * 2;
            float b0 = bv[col], b1 = bv[col + 1];
            int row = row0 + warp_m * 32 + mf * 16 + qr;
            if (row < NN) {
                float2 v = make_float2(acc[mf][nf][0] + b0, acc[mf][nf][1] + b1);
                *(float2*)(out + (size_t)row * HC + col) = v;
            }
            if (row + 8 < NN) {
                float2 v = make_float2(acc[mf][nf][2] + b0, acc[mf][nf][3] + b1);
                *(float2*)(out + (size_t)(row + 8) * HC + col) = v;
            }
        }
    }
}

// ---------------------------------------------------------------------------
// Float atomic max via monotonic int/uint trick (init must be -inf)
// ---------------------------------------------------------------------------
__device__ __forceinline__ void atomicMaxF(float* addr, float v) {
    if (v >= 0.0f)
        atomicMax((int*)addr, __float_as_int(v));
    else
        atomicMin((unsigned int*)addr, __float_as_uint(v));
}

// ---------------------------------------------------------------------------
// Pass B: per-edge logits + segment max.
// One warp per edge. Lane l reads float4 at channel 4l; lanes 0-15 = head0,
// lanes 16-31 = head1. Width-16 shuffle reduction per head.
// ---------------------------------------------------------------------------
__global__ void __launch_bounds__(256) edge_logits_kernel(
    const int* __restrict__ ei, const float* __restrict__ att)
{
    int e = blockIdx.x * 8 + (threadIdx.x >> 5);
    if (e >= ETOT) return;
    int lane = threadIdx.x & 31;

    int src, dst;
    if (e < EBASE) { src = __ldg(ei + e); dst = __ldg(ei + EBASE + e); }
    else           { src = e - EBASE;     dst = src; }

    float4 a = *(const float4*)(d_xl + (size_t)src * HC + lane * 4);
    float4 b = *(const float4*)(d_xr + (size_t)dst * HC + lane * 4);
    float4 w = *(const float4*)(att + lane * 4);

    float e0 = a.x + b.x, e1 = a.y + b.y, e2 = a.z + b.z, e3 = a.w + b.w;
    e0 = e0 > 0.f ? e0 : 0.2f * e0;
    e1 = e1 > 0.f ? e1 : 0.2f * e1;
    e2 = e2 > 0.f ? e2 : 0.2f * e2;
    e3 = e3 > 0.f ? e3 : 0.2f * e3;
    float s = w.x * e0 + w.y * e1 + w.z * e2 + w.w * e3;

    // reduce within each 16-lane half (one per head)
    s += __shfl_down_sync(0xffffffffu, s, 8, 16);
    s += __shfl_down_sync(0xffffffffu, s, 4, 16);
    s += __shfl_down_sync(0xffffffffu, s, 2, 16);
    s += __shfl_down_sync(0xffffffffu, s, 1, 16);

    if (lane == 0) {
        d_p[(size_t)e * 2 + 0] = s;
        atomicMaxF(&d_m[(size_t)dst * 2 + 0], s);
    } else if (lane == 16) {
        d_p[(size_t)e * 2 + 1] = s;
        atomicMaxF(&d_m[(size_t)dst * 2 + 1], s);
    }
}

// ---------------------------------------------------------------------------
// Pass C+D fused: p = exp(logit - m[dst]); den += p; out += p * xl[src].
// Normalization (divide by den) is deferred to the finalize kernel — the
// result is algebraically identical since den doesn't depend on the edge.
// One warp per edge; vector red.global.add for the feature accumulation.
// ---------------------------------------------------------------------------
__global__ void __launch_bounds__(256) edge_aggregate_kernel(
    const int* __restrict__ ei, float* __restrict__ out)
{
    int e = blockIdx.x * 8 + (threadIdx.x >> 5);
    if (e >= ETOT) return;
    int lane = threadIdx.x & 31;

    int src, dst;
    if (e < EBASE) { src = __ldg(ei + e); dst = __ldg(ei + EBASE + e); }
    else           { src = e - EBASE;     dst = src; }

    int h = lane >> 4;   // head for this lane's channels
    float lg = d_p[(size_t)e * 2 + h];          // 2 addrs/warp, broadcast
    float m  = d_m[(size_t)dst * 2 + h];
    float p  = __expf(lg - m);

    if (lane == 0 || lane == 16)
        atomicAdd(&d_den[(size_t)dst * 2 + h], p);

    float4 v = *(const float4*)(d_xl + (size_t)src * HC + lane * 4);
    float vx = v.x * p, vy = v.y * p, vz = v.z * p, vw = v.w * p;
    float* o = out + (size_t)dst * HC + lane * 4;
    asm volatile("red.global.add.v4.f32 [%0], {%1, %2, %3, %4};"
                 :: "l"(o), "f"(vx), "f"(vy), "f"(vz), "f"(vw)
                 : "memory");
}

// ---------------------------------------------------------------------------
// Finalize: out[n, c] = out[n, c] / den[n, head(c)] + bias[c]
// ---------------------------------------------------------------------------
__global__ void finalize_kernel(float* __restrict__ out,
                                const float* __restrict__ bias)
{
    int i = blockIdx.x * 256 + threadIdx.x;        // float4 index
    if (i >= NN * (HC / 4)) return;
    int n = i >> 5;                                // node (32 float4s per node)
    int c = (i & 31) * 4;                          // channel of .x
    int h = c >> 6;                                // head (C=64)
    float inv = 1.0f / d_den[(size_t)n * 2 + h];   // one head per float4 (c..c+3)
    float4 v = ((float4*)out)[i];
    v.x = v.x * inv + bias[c];
    v.y = v.y * inv + bias[c + 1];
    v.z = v.z * inv + bias[c + 2];
    v.w = v.w * inv + bias[c + 3];
    ((float4*)out)[i] = v;
}

// ---------------------------------------------------------------------------
// Launch
// ---------------------------------------------------------------------------
extern "C" void kernel_launch(void* const* d_in, const int* in_sizes, int n_in,
                              void* d_out, int out_size)
{
    const float* x    = (const float*)d_in[0];
    const float* Wl   = (const float*)d_in[1];
    const float* bl   = (const float*)d_in[2];
    const float* Wr   = (const float*)d_in[3];
    const float* br   = (const float*)d_in[4];
    const float* att  = (const float*)d_in[5];
    const float* bias = (const float*)d_in[6];
    const int*   ei   = (const int*)d_in[7];
    float* out = (float*)d_out;

    // 1) init out=0, m=-inf, den=0
    init_kernel<<<(NN * (HC / 4) + 255) / 256, 256>>>(out);

    // 2) fused projections xl + xr (TF32 tensor cores, single pass over x)
    proj_fused_kernel<<<(NN + 127) / 128, 512>>>(x, Wl, bl, Wr, br);

    // 3) per-edge logits + segment max
    edge_logits_kernel<<<(ETOT + 7) / 8, 256>>>(ei, att);

    // 4) fused exp + denom + weighted scatter-add
    edge_aggregate_kernel<<<(ETOT + 7) / 8, 256>>>(ei, out);

    // 5) normalize + bias
    finalize_kernel<<<(NN * (HC / 4) + 255) / 256, 256>>>(out, bias);
}